// round 2
// baseline (speedup 1.0000x reference)
#include <cuda_runtime.h>

#define DM   768
#define NH   12
#define DH   64
#define BB   2
#define TT   4096
#define BH   (BB*NH)

// Scratch (no cudaMalloc allowed): Q/K/V in [B,H,T,Dh], att in [B,T,H,Dh]
__device__ float g_Q[(size_t)BH*TT*DH];
__device__ float g_K[(size_t)BH*TT*DH];
__device__ float g_V[(size_t)BH*TT*DH];
__device__ float g_att[(size_t)BB*TT*DM];

// ---------------------------------------------------------------------------
// GEMM1: qkv = x @ w_qkv^T + b_qkv, scattered into g_Q/g_K/g_V.
// C[m,n] = sum_k x[m,k]*w[n,k].  Tiles 64x64, K-tile 16, 256 thr, 4x4/thread.
// n0 is 64-aligned -> (which, head) constant per block, d = local col.
// Q values pre-scaled by 1/sqrt(64) = 0.125.
// ---------------------------------------------------------------------------
__global__ __launch_bounds__(256) void qkv_kernel(const float* __restrict__ x,
                                                  const float* __restrict__ w,
                                                  const float* __restrict__ bias) {
    __shared__ float As[16][64];   // [k][m]
    __shared__ float Ws[16][64];   // [k][n]
    const int tid = threadIdx.x;
    const int tx = tid & 15, ty = tid >> 4;
    const int n0 = blockIdx.x * 64, m0 = blockIdx.y * 64;
    const int lr = tid >> 2, lk = (tid & 3) * 4;

    const float* aptr = x + (size_t)(m0 + lr) * DM + lk;
    const float* wptr = w + (size_t)(n0 + lr) * DM + lk;

    float acc[4][4] = {};
    for (int k0 = 0; k0 < DM; k0 += 16) {
        float4 a4 = *(const float4*)(aptr + k0);
        float4 w4 = *(const float4*)(wptr + k0);
        As[lk + 0][lr] = a4.x; As[lk + 1][lr] = a4.y;
        As[lk + 2][lr] = a4.z; As[lk + 3][lr] = a4.w;
        Ws[lk + 0][lr] = w4.x; Ws[lk + 1][lr] = w4.y;
        Ws[lk + 2][lr] = w4.z; Ws[lk + 3][lr] = w4.w;
        __syncthreads();
#pragma unroll
        for (int k = 0; k < 16; k++) {
            float a[4], b[4];
            *(float4*)a = *(float4*)&As[k][4 * ty];
            *(float4*)b = *(float4*)&Ws[k][4 * tx];
#pragma unroll
            for (int i = 0; i < 4; i++)
#pragma unroll
                for (int j = 0; j < 4; j++)
                    acc[i][j] += a[i] * b[j];
        }
        __syncthreads();
    }

    const int which = n0 / DM;              // 0=Q 1=K 2=V
    const int head  = (n0 % DM) >> 6;
    float* dst = (which == 0) ? g_Q : ((which == 1) ? g_K : g_V);
    const float scale = (which == 0) ? 0.125f : 1.0f;

    float bia[4];
#pragma unroll
    for (int j = 0; j < 4; j++) bia[j] = bias[n0 + 4 * tx + j];

#pragma unroll
    for (int i = 0; i < 4; i++) {
        int m = m0 + 4 * ty + i;
        int bb = m >> 12, t = m & 4095;
        size_t base = (((size_t)(bb * NH + head)) * TT + t) * DH + 4 * tx;
        float4 o;
        o.x = (acc[i][0] + bia[0]) * scale;
        o.y = (acc[i][1] + bia[1]) * scale;
        o.z = (acc[i][2] + bia[2]) * scale;
        o.w = (acc[i][3] + bia[3]) * scale;
        *(float4*)&dst[base] = o;
    }
}

// ---------------------------------------------------------------------------
// Flash attention: block = (q-tile 64, one (b,h)). 256 threads, 4x4 outputs.
// Qt/Kt stored d-major in smem (conflict-free float4 in the dot loop).
// Softmax stats (m,l) live in registers, reduced across 16 tx lanes by shfl.
// P staged transposed with stride 68 (16B-aligned rows, ~conflict-free reads).
// ---------------------------------------------------------------------------
__global__ __launch_bounds__(256) void attn_kernel(const int* __restrict__ mask,
                                                   float* __restrict__ att) {
    extern __shared__ float sm[];
    float* Qt = sm;                 // Qt[d*64 + r]
    float* Kt = sm + 64 * 64;       // Kt[d*64 + c]
    float* Vs = sm + 2 * 64 * 64;   // Vs[k*64 + c]
    float* Pt = sm + 3 * 64 * 64;   // Pt[c*68 + r]

    const int tid = threadIdx.x;
    const int tx = tid & 15, ty = tid >> 4;
    const int bh = blockIdx.y;
    const int b = bh / NH, head = bh % NH;
    const int q0 = blockIdx.x * 64;

    const float* Qp = g_Q + (size_t)bh * TT * DH;
    const float* Kp = g_K + (size_t)bh * TT * DH;
    const float* Vp = g_V + (size_t)bh * TT * DH;
    const int* mrow_g = mask + (size_t)b * TT;

    // load Q tile transposed
    {
        int r = tid >> 2, d0 = (tid & 3) * 16;
        const float* src = Qp + (size_t)(q0 + r) * DH + d0;
#pragma unroll
        for (int u = 0; u < 4; u++) {
            float4 v = *(const float4*)(src + 4 * u);
            Qt[(d0 + 4 * u + 0) * 64 + r] = v.x;
            Qt[(d0 + 4 * u + 1) * 64 + r] = v.y;
            Qt[(d0 + 4 * u + 2) * 64 + r] = v.z;
            Qt[(d0 + 4 * u + 3) * 64 + r] = v.w;
        }
    }

    float O[4][4] = {};
    float mr[4], lr_[4];
#pragma unroll
    for (int i = 0; i < 4; i++) { mr[i] = -1e30f; lr_[i] = 0.f; }

    for (int jt = 0; jt < TT / 64; jt++) {
        __syncthreads();           // prev PV done (and Qt visible on iter 0)
        // load K (transposed) and V (natural)
        {
            int r = tid >> 2, d0 = (tid & 3) * 16;
            const float* ks = Kp + (size_t)(jt * 64 + r) * DH + d0;
            const float* vs = Vp + (size_t)(jt * 64 + r) * DH + d0;
#pragma unroll
            for (int u = 0; u < 4; u++) {
                float4 kv = *(const float4*)(ks + 4 * u);
                Kt[(d0 + 4 * u + 0) * 64 + r] = kv.x;
                Kt[(d0 + 4 * u + 1) * 64 + r] = kv.y;
                Kt[(d0 + 4 * u + 2) * 64 + r] = kv.z;
                Kt[(d0 + 4 * u + 3) * 64 + r] = kv.w;
                *(float4*)&Vs[r * 64 + d0 + 4 * u] = *(const float4*)(vs + 4 * u);
            }
        }
        __syncthreads();

        // S = Q @ K^T  (Q pre-scaled by 1/sqrt(DH))
        float s[4][4] = {};
#pragma unroll 8
        for (int d = 0; d < 64; d++) {
            float q[4], k[4];
            *(float4*)q = *(float4*)&Qt[d * 64 + 4 * ty];
            *(float4*)k = *(float4*)&Kt[d * 64 + 4 * tx];
#pragma unroll
            for (int i = 0; i < 4; i++)
#pragma unroll
                for (int j = 0; j < 4; j++)
                    s[i][j] += q[i] * k[j];
        }

        // mask (key dim)
        {
            int kc = jt * 64 + 4 * tx;
#pragma unroll
            for (int j = 0; j < 4; j++) {
                if (mrow_g[kc + j] == 0) {
#pragma unroll
                    for (int i = 0; i < 4; i++) s[i][j] = -1e9f;
                }
            }
        }

        // online softmax: stats per row, replicated across the 16 tx lanes
#pragma unroll
        for (int i = 0; i < 4; i++) {
            float mx = fmaxf(fmaxf(s[i][0], s[i][1]), fmaxf(s[i][2], s[i][3]));
            mx = fmaxf(mx, __shfl_xor_sync(0xffffffffu, mx, 1));
            mx = fmaxf(mx, __shfl_xor_sync(0xffffffffu, mx, 2));
            mx = fmaxf(mx, __shfl_xor_sync(0xffffffffu, mx, 4));
            mx = fmaxf(mx, __shfl_xor_sync(0xffffffffu, mx, 8));
            float mnew = fmaxf(mr[i], mx);
            float alpha = __expf(mr[i] - mnew);
            float sum = 0.f;
#pragma unroll
            for (int j = 0; j < 4; j++) {
                s[i][j] = __expf(s[i][j] - mnew);
                sum += s[i][j];
            }
            sum += __shfl_xor_sync(0xffffffffu, sum, 1);
            sum += __shfl_xor_sync(0xffffffffu, sum, 2);
            sum += __shfl_xor_sync(0xffffffffu, sum, 4);
            sum += __shfl_xor_sync(0xffffffffu, sum, 8);
            lr_[i] = lr_[i] * alpha + sum;
            mr[i] = mnew;
#pragma unroll
            for (int j = 0; j < 4; j++) O[i][j] *= alpha;
            // store P transposed: Pt[c][r], stride 68
#pragma unroll
            for (int j = 0; j < 4; j++)
                Pt[(4 * tx + j) * 68 + 4 * ty + i] = s[i][j];
        }
        __syncthreads();

        // O += P @ V
#pragma unroll 8
        for (int k = 0; k < 64; k++) {
            float p[4], v[4];
            *(float4*)p = *(float4*)&Pt[k * 68 + 4 * ty];
            *(float4*)v = *(float4*)&Vs[k * 64 + 4 * tx];
#pragma unroll
            for (int i = 0; i < 4; i++)
#pragma unroll
                for (int j = 0; j < 4; j++)
                    O[i][j] += p[i] * v[j];
        }
    }

    // write att in [B, T, H, Dh]
#pragma unroll
    for (int i = 0; i < 4; i++) {
        float inv = 1.0f / lr_[i];
        int t = q0 + 4 * ty + i;
        size_t base = (((size_t)b * TT + t) * NH + head) * DH + 4 * tx;
        float4 o;
        o.x = O[i][0] * inv; o.y = O[i][1] * inv;
        o.z = O[i][2] * inv; o.w = O[i][3] * inv;
        *(float4*)&att[base] = o;
    }
}

// ---------------------------------------------------------------------------
// GEMM2: out = att @ w_out^T + b_out, plain row-major output.
// ---------------------------------------------------------------------------
__global__ __launch_bounds__(256) void out_kernel(const float* __restrict__ a_in,
                                                  const float* __restrict__ w,
                                                  const float* __restrict__ bias,
                                                  float* __restrict__ out) {
    __shared__ float As[16][64];
    __shared__ float Ws[16][64];
    const int tid = threadIdx.x;
    const int tx = tid & 15, ty = tid >> 4;
    const int n0 = blockIdx.x * 64, m0 = blockIdx.y * 64;
    const int lr = tid >> 2, lk = (tid & 3) * 4;

    const float* aptr = a_in + (size_t)(m0 + lr) * DM + lk;
    const float* wptr = w + (size_t)(n0 + lr) * DM + lk;

    float acc[4][4] = {};
    for (int k0 = 0; k0 < DM; k0 += 16) {
        float4 a4 = *(const float4*)(aptr + k0);
        float4 w4 = *(const float4*)(wptr + k0);
        As[lk + 0][lr] = a4.x; As[lk + 1][lr] = a4.y;
        As[lk + 2][lr] = a4.z; As[lk + 3][lr] = a4.w;
        Ws[lk + 0][lr] = w4.x; Ws[lk + 1][lr] = w4.y;
        Ws[lk + 2][lr] = w4.z; Ws[lk + 3][lr] = w4.w;
        __syncthreads();
#pragma unroll
        for (int k = 0; k < 16; k++) {
            float a[4], b[4];
            *(float4*)a = *(float4*)&As[k][4 * ty];
            *(float4*)b = *(float4*)&Ws[k][4 * tx];
#pragma unroll
            for (int i = 0; i < 4; i++)
#pragma unroll
                for (int j = 0; j < 4; j++)
                    acc[i][j] += a[i] * b[j];
        }
        __syncthreads();
    }

    float bia[4];
#pragma unroll
    for (int j = 0; j < 4; j++) bia[j] = bias[n0 + 4 * tx + j];

#pragma unroll
    for (int i = 0; i < 4; i++) {
        int m = m0 + 4 * ty + i;
        float4 o;
        o.x = acc[i][0] + bia[0];
        o.y = acc[i][1] + bia[1];
        o.z = acc[i][2] + bia[2];
        o.w = acc[i][3] + bia[3];
        *(float4*)&out[(size_t)m * DM + n0 + 4 * tx] = o;
    }
}

// ---------------------------------------------------------------------------
// Inputs (metadata order): x, w_qkv, b_qkv, w_out, b_out, mask. Output: float32.
// ---------------------------------------------------------------------------
extern "C" void kernel_launch(void* const* d_in, const int* in_sizes, int n_in,
                              void* d_out, int out_size) {
    const float* x     = (const float*)d_in[0];
    const float* w_qkv = (const float*)d_in[1];
    const float* b_qkv = (const float*)d_in[2];
    const float* w_out = (const float*)d_in[3];
    const float* b_out = (const float*)d_in[4];
    const int*   mask  = (const int*)d_in[5];
    float* out = (float*)d_out;

    static const size_t ATTN_SMEM = (3 * 64 * 64 + 64 * 68) * sizeof(float); // 66560
    cudaFuncSetAttribute(attn_kernel, cudaFuncAttributeMaxDynamicSharedMemorySize,
                         (int)ATTN_SMEM);

    float* att;
    cudaGetSymbolAddress((void**)&att, g_att);

    qkv_kernel<<<dim3(3 * DM / 64, BB * TT / 64), 256>>>(x, w_qkv, b_qkv);
    attn_kernel<<<dim3(TT / 64, BH), 256, ATTN_SMEM>>>(mask, att);
    out_kernel<<<dim3(DM / 64, BB * TT / 64), 256>>>(att, w_out, b_out, out);
}

// round 3
// speedup vs baseline: 1.0937x; 1.0937x over previous
#include <cuda_runtime.h>

#define DM   768
#define NH   12
#define DH   64
#define BB   2
#define TT   4096
#define BH   (BB*NH)

// Scratch (no cudaMalloc allowed): Q/K/V in [B,H,T,Dh], att in [B,T,H,Dh]
__device__ float g_Q[(size_t)BH*TT*DH];
__device__ float g_K[(size_t)BH*TT*DH];
__device__ float g_V[(size_t)BH*TT*DH];
__device__ float g_att[(size_t)BB*TT*DM];

// ---------------------------------------------------------------------------
// GEMM1: qkv = x @ w_qkv^T + b_qkv, scattered into g_Q/g_K/g_V.
// 128x128 tile, K-tile 16, 256 threads, 8x8 per thread (1 B LDS per FMA).
// Q pre-scaled by 1/sqrt(64) = 0.125.
// ---------------------------------------------------------------------------
__global__ __launch_bounds__(256) void qkv_kernel(const float* __restrict__ x,
                                                  const float* __restrict__ w,
                                                  const float* __restrict__ bias) {
    __shared__ float As[16][128];
    __shared__ float Ws[16][128];
    const int tid = threadIdx.x;
    const int tx = tid & 15, ty = tid >> 4;
    const int n0 = blockIdx.x * 128, m0 = blockIdx.y * 128;
    const int lr = tid >> 2, lk = (tid & 3) * 4;

    const float* a0p = x + (size_t)(m0 + lr) * DM + lk;
    const float* a1p = a0p + (size_t)64 * DM;
    const float* w0p = w + (size_t)(n0 + lr) * DM + lk;
    const float* w1p = w0p + (size_t)64 * DM;

    float4 ra0 = *(const float4*)a0p;
    float4 ra1 = *(const float4*)a1p;
    float4 rw0 = *(const float4*)w0p;
    float4 rw1 = *(const float4*)w1p;

    float acc[8][8] = {};
    for (int k0 = 0; k0 < DM; k0 += 16) {
        As[lk + 0][lr] = ra0.x; As[lk + 1][lr] = ra0.y;
        As[lk + 2][lr] = ra0.z; As[lk + 3][lr] = ra0.w;
        As[lk + 0][lr + 64] = ra1.x; As[lk + 1][lr + 64] = ra1.y;
        As[lk + 2][lr + 64] = ra1.z; As[lk + 3][lr + 64] = ra1.w;
        Ws[lk + 0][lr] = rw0.x; Ws[lk + 1][lr] = rw0.y;
        Ws[lk + 2][lr] = rw0.z; Ws[lk + 3][lr] = rw0.w;
        Ws[lk + 0][lr + 64] = rw1.x; Ws[lk + 1][lr + 64] = rw1.y;
        Ws[lk + 2][lr + 64] = rw1.z; Ws[lk + 3][lr + 64] = rw1.w;
        __syncthreads();
        int knext = (k0 + 16 < DM) ? (k0 + 16) : 0;   // last prefetch harmless
        ra0 = *(const float4*)(a0p + knext);
        ra1 = *(const float4*)(a1p + knext);
        rw0 = *(const float4*)(w0p + knext);
        rw1 = *(const float4*)(w1p + knext);
#pragma unroll
        for (int k = 0; k < 16; k++) {
            float a[8], b[8];
            *(float4*)&a[0] = *(const float4*)&As[k][8 * ty];
            *(float4*)&a[4] = *(const float4*)&As[k][8 * ty + 4];
            *(float4*)&b[0] = *(const float4*)&Ws[k][8 * tx];
            *(float4*)&b[4] = *(const float4*)&Ws[k][8 * tx + 4];
#pragma unroll
            for (int i = 0; i < 8; i++)
#pragma unroll
                for (int j = 0; j < 8; j++)
                    acc[i][j] += a[i] * b[j];
        }
        __syncthreads();
    }

    const int g = n0 + 8 * tx;
    const int which = n0 / DM;              // 0=Q 1=K 2=V (tiles never straddle)
    const int head  = (g % DM) >> 6;
    const int d0    = g & 63;
    float* dst = (which == 0) ? g_Q : ((which == 1) ? g_K : g_V);
    const float scale = (which == 0) ? 0.125f : 1.0f;

    float bia[8];
    *(float4*)&bia[0] = *(const float4*)&bias[g];
    *(float4*)&bia[4] = *(const float4*)&bias[g + 4];

#pragma unroll
    for (int i = 0; i < 8; i++) {
        int m = m0 + 8 * ty + i;
        int bb = m >> 12, t = m & 4095;
        float* o = &dst[(((size_t)(bb * NH + head)) * TT + t) * DH + d0];
        float4 v0, v1;
        v0.x = (acc[i][0] + bia[0]) * scale; v0.y = (acc[i][1] + bia[1]) * scale;
        v0.z = (acc[i][2] + bia[2]) * scale; v0.w = (acc[i][3] + bia[3]) * scale;
        v1.x = (acc[i][4] + bia[4]) * scale; v1.y = (acc[i][5] + bia[5]) * scale;
        v1.z = (acc[i][6] + bia[6]) * scale; v1.w = (acc[i][7] + bia[7]) * scale;
        *(float4*)o = v0;
        *(float4*)(o + 4) = v1;
    }
}

// ---------------------------------------------------------------------------
// Flash attention: 128 q-rows x 128 k-cols per iteration, 256 threads.
// S phase: 8x8 fragments (rows 8ty+i, cols 8tx+j); softmax reduced over tx
//          lanes (in-warp shfl). P stored row-major, stride 132.
// PV phase: remapped 4x8 fragments (rows ro+32i, d-cols 8dx) -> conflict-free
//          float4 P reads and single-wavefront V reads. alpha/l cross the
//          mapping via smem.
// ---------------------------------------------------------------------------
__global__ __launch_bounds__(256) void attn_kernel(const int* __restrict__ mask,
                                                   float* __restrict__ att) {
    extern __shared__ float sm[];
    float* Qt = sm;                    // [64][128]  d-major
    float* Kt = Qt + 64 * 128;         // [64][128]  d-major
    float* Vs = Kt + 64 * 128;         // [128][64]  k-major
    float* Pt = Vs + 128 * 64;         // [128][132] q-major, padded
    float* alpha_s = Pt + 128 * 132;   // [128]

    const int tid = threadIdx.x;
    const int tx = tid & 15, ty = tid >> 4;   // S mapping
    const int dx = tid & 7,  ro = tid >> 3;   // PV mapping
    const int bh = blockIdx.y;
    const int b = bh / NH, head = bh % NH;
    const int q0 = blockIdx.x * 128;

    const float* Qp = g_Q + (size_t)bh * TT * DH;
    const float* Kp = g_K + (size_t)bh * TT * DH;
    const float* Vp = g_V + (size_t)bh * TT * DH;
    const int* mrow_g = mask + (size_t)b * TT;

    // load Q tile transposed (rows r, r+64)
    {
        int r = tid >> 2, d0 = (tid & 3) * 16;
#pragma unroll
        for (int h = 0; h < 2; h++) {
            int rr = r + 64 * h;
            const float* src = Qp + (size_t)(q0 + rr) * DH + d0;
#pragma unroll
            for (int u = 0; u < 4; u++) {
                float4 v = *(const float4*)(src + 4 * u);
                Qt[(d0 + 4 * u + 0) * 128 + rr] = v.x;
                Qt[(d0 + 4 * u + 1) * 128 + rr] = v.y;
                Qt[(d0 + 4 * u + 2) * 128 + rr] = v.z;
                Qt[(d0 + 4 * u + 3) * 128 + rr] = v.w;
            }
        }
    }

    float O[4][8] = {};
    float mr[8], lw[8];
#pragma unroll
    for (int i = 0; i < 8; i++) { mr[i] = -1e30f; lw[i] = 0.f; }

    for (int jt = 0; jt < TT / 128; jt++) {
        __syncthreads();   // prev PV done; (iter 0: Qt load visible after next)
        {
            int r = tid >> 2, d0 = (tid & 3) * 16;
#pragma unroll
            for (int h = 0; h < 2; h++) {
                int rr = r + 64 * h;
                const float* ks = Kp + (size_t)(jt * 128 + rr) * DH + d0;
                const float* vs = Vp + (size_t)(jt * 128 + rr) * DH + d0;
#pragma unroll
                for (int u = 0; u < 4; u++) {
                    float4 kv = *(const float4*)(ks + 4 * u);
                    Kt[(d0 + 4 * u + 0) * 128 + rr] = kv.x;
                    Kt[(d0 + 4 * u + 1) * 128 + rr] = kv.y;
                    Kt[(d0 + 4 * u + 2) * 128 + rr] = kv.z;
                    Kt[(d0 + 4 * u + 3) * 128 + rr] = kv.w;
                    *(float4*)&Vs[rr * 64 + d0 + 4 * u] = *(const float4*)(vs + 4 * u);
                }
            }
        }
        int msk[8];
        {
            const int* mp = mrow_g + jt * 128 + 8 * tx;
            *(int4*)&msk[0] = *(const int4*)mp;
            *(int4*)&msk[4] = *(const int4*)(mp + 4);
        }
        __syncthreads();

        // S = Q @ K^T  (Q pre-scaled)
        float s[8][8] = {};
#pragma unroll 8
        for (int d = 0; d < 64; d++) {
            float q[8], k[8];
            *(float4*)&q[0] = *(const float4*)&Qt[d * 128 + 8 * ty];
            *(float4*)&q[4] = *(const float4*)&Qt[d * 128 + 8 * ty + 4];
            *(float4*)&k[0] = *(const float4*)&Kt[d * 128 + 8 * tx];
            *(float4*)&k[4] = *(const float4*)&Kt[d * 128 + 8 * tx + 4];
#pragma unroll
            for (int i = 0; i < 8; i++)
#pragma unroll
                for (int j = 0; j < 8; j++)
                    s[i][j] += q[i] * k[j];
        }
#pragma unroll
        for (int j = 0; j < 8; j++) {
            if (msk[j] == 0) {
#pragma unroll
                for (int i = 0; i < 8; i++) s[i][j] = -1e9f;
            }
        }

        // online softmax (rows 8ty+i), reduce over tx lanes
#pragma unroll
        for (int i = 0; i < 8; i++) {
            float mx = s[i][0];
#pragma unroll
            for (int j = 1; j < 8; j++) mx = fmaxf(mx, s[i][j]);
            mx = fmaxf(mx, __shfl_xor_sync(0xffffffffu, mx, 1));
            mx = fmaxf(mx, __shfl_xor_sync(0xffffffffu, mx, 2));
            mx = fmaxf(mx, __shfl_xor_sync(0xffffffffu, mx, 4));
            mx = fmaxf(mx, __shfl_xor_sync(0xffffffffu, mx, 8));
            float mnew = fmaxf(mr[i], mx);
            float al = __expf(mr[i] - mnew);
            float sum = 0.f;
#pragma unroll
            for (int j = 0; j < 8; j++) {
                s[i][j] = __expf(s[i][j] - mnew);
                sum += s[i][j];
            }
            sum += __shfl_xor_sync(0xffffffffu, sum, 1);
            sum += __shfl_xor_sync(0xffffffffu, sum, 2);
            sum += __shfl_xor_sync(0xffffffffu, sum, 4);
            sum += __shfl_xor_sync(0xffffffffu, sum, 8);
            lw[i] = lw[i] * al + sum;
            mr[i] = mnew;
            if (tx == 0) alpha_s[8 * ty + i] = al;
            float* prow = &Pt[(8 * ty + i) * 132 + 8 * tx];
            *(float4*)prow       = make_float4(s[i][0], s[i][1], s[i][2], s[i][3]);
            *(float4*)(prow + 4) = make_float4(s[i][4], s[i][5], s[i][6], s[i][7]);
        }
        __syncthreads();

        // O = O*alpha + P @ V   (rows ro+32i, cols 8dx..8dx+7)
        float al4[4];
#pragma unroll
        for (int i = 0; i < 4; i++) al4[i] = alpha_s[ro + 32 * i];
#pragma unroll
        for (int i = 0; i < 4; i++)
#pragma unroll
            for (int j = 0; j < 8; j++) O[i][j] *= al4[i];

#pragma unroll 2
        for (int k4 = 0; k4 < 128; k4 += 4) {
            float p[4][4];
#pragma unroll
            for (int i = 0; i < 4; i++)
                *(float4*)p[i] = *(const float4*)&Pt[(ro + 32 * i) * 132 + k4];
#pragma unroll
            for (int u = 0; u < 4; u++) {
                float v[8];
                *(float4*)&v[0] = *(const float4*)&Vs[(k4 + u) * 64 + 8 * dx];
                *(float4*)&v[4] = *(const float4*)&Vs[(k4 + u) * 64 + 8 * dx + 4];
#pragma unroll
                for (int i = 0; i < 4; i++)
#pragma unroll
                    for (int j = 0; j < 8; j++)
                        O[i][j] += p[i][u] * v[j];
            }
        }
    }

    // epilogue: 1/l across the mapping, then store [B,T,H,Dh]
    __syncthreads();
    if (tx == 0) {
#pragma unroll
        for (int i = 0; i < 8; i++) alpha_s[8 * ty + i] = 1.0f / lw[i];
    }
    __syncthreads();
#pragma unroll
    for (int i = 0; i < 4; i++) {
        float inv = alpha_s[ro + 32 * i];
        int t = q0 + ro + 32 * i;
        float* o = att + (((size_t)b * TT + t) * NH + head) * DH + 8 * dx;
        float4 v0, v1;
        v0.x = O[i][0] * inv; v0.y = O[i][1] * inv;
        v0.z = O[i][2] * inv; v0.w = O[i][3] * inv;
        v1.x = O[i][4] * inv; v1.y = O[i][5] * inv;
        v1.z = O[i][6] * inv; v1.w = O[i][7] * inv;
        *(float4*)o = v0;
        *(float4*)(o + 4) = v1;
    }
}

// ---------------------------------------------------------------------------
// GEMM2: out = att @ w_out^T + b_out. Same 128x128x16 microkernel.
// ---------------------------------------------------------------------------
__global__ __launch_bounds__(256) void out_kernel(const float* __restrict__ a_in,
                                                  const float* __restrict__ w,
                                                  const float* __restrict__ bias,
                                                  float* __restrict__ out) {
    __shared__ float As[16][128];
    __shared__ float Ws[16][128];
    const int tid = threadIdx.x;
    const int tx = tid & 15, ty = tid >> 4;
    const int n0 = blockIdx.x * 128, m0 = blockIdx.y * 128;
    const int lr = tid >> 2, lk = (tid & 3) * 4;

    const float* a0p = a_in + (size_t)(m0 + lr) * DM + lk;
    const float* a1p = a0p + (size_t)64 * DM;
    const float* w0p = w + (size_t)(n0 + lr) * DM + lk;
    const float* w1p = w0p + (size_t)64 * DM;

    float4 ra0 = *(const float4*)a0p;
    float4 ra1 = *(const float4*)a1p;
    float4 rw0 = *(const float4*)w0p;
    float4 rw1 = *(const float4*)w1p;

    float acc[8][8] = {};
    for (int k0 = 0; k0 < DM; k0 += 16) {
        As[lk + 0][lr] = ra0.x; As[lk + 1][lr] = ra0.y;
        As[lk + 2][lr] = ra0.z; As[lk + 3][lr] = ra0.w;
        As[lk + 0][lr + 64] = ra1.x; As[lk + 1][lr + 64] = ra1.y;
        As[lk + 2][lr + 64] = ra1.z; As[lk + 3][lr + 64] = ra1.w;
        Ws[lk + 0][lr] = rw0.x; Ws[lk + 1][lr] = rw0.y;
        Ws[lk + 2][lr] = rw0.z; Ws[lk + 3][lr] = rw0.w;
        Ws[lk + 0][lr + 64] = rw1.x; Ws[lk + 1][lr + 64] = rw1.y;
        Ws[lk + 2][lr + 64] = rw1.z; Ws[lk + 3][lr + 64] = rw1.w;
        __syncthreads();
        int knext = (k0 + 16 < DM) ? (k0 + 16) : 0;
        ra0 = *(const float4*)(a0p + knext);
        ra1 = *(const float4*)(a1p + knext);
        rw0 = *(const float4*)(w0p + knext);
        rw1 = *(const float4*)(w1p + knext);
#pragma unroll
        for (int k = 0; k < 16; k++) {
            float a[8], b[8];
            *(float4*)&a[0] = *(const float4*)&As[k][8 * ty];
            *(float4*)&a[4] = *(const float4*)&As[k][8 * ty + 4];
            *(float4*)&b[0] = *(const float4*)&Ws[k][8 * tx];
            *(float4*)&b[4] = *(const float4*)&Ws[k][8 * tx + 4];
#pragma unroll
            for (int i = 0; i < 8; i++)
#pragma unroll
                for (int j = 0; j < 8; j++)
                    acc[i][j] += a[i] * b[j];
        }
        __syncthreads();
    }

    float bia[8];
    *(float4*)&bia[0] = *(const float4*)&bias[n0 + 8 * tx];
    *(float4*)&bia[4] = *(const float4*)&bias[n0 + 8 * tx + 4];

#pragma unroll
    for (int i = 0; i < 8; i++) {
        int m = m0 + 8 * ty + i;
        float* o = &out[(size_t)m * DM + n0 + 8 * tx];
        float4 v0, v1;
        v0.x = acc[i][0] + bia[0]; v0.y = acc[i][1] + bia[1];
        v0.z = acc[i][2] + bia[2]; v0.w = acc[i][3] + bia[3];
        v1.x = acc[i][4] + bia[4]; v1.y = acc[i][5] + bia[5];
        v1.z = acc[i][6] + bia[6]; v1.w = acc[i][7] + bia[7];
        *(float4*)o = v0;
        *(float4*)(o + 4) = v1;
    }
}

// ---------------------------------------------------------------------------
// Inputs (metadata order): x, w_qkv, b_qkv, w_out, b_out, mask. Output: float32.
// ---------------------------------------------------------------------------
extern "C" void kernel_launch(void* const* d_in, const int* in_sizes, int n_in,
                              void* d_out, int out_size) {
    const float* x     = (const float*)d_in[0];
    const float* w_qkv = (const float*)d_in[1];
    const float* b_qkv = (const float*)d_in[2];
    const float* w_out = (const float*)d_in[3];
    const float* b_out = (const float*)d_in[4];
    const int*   mask  = (const int*)d_in[5];
    float* out = (float*)d_out;

    static const size_t ATTN_SMEM =
        (2 * 64 * 128 + 128 * 64 + 128 * 132 + 128) * sizeof(float); // 166912 B
    cudaFuncSetAttribute(attn_kernel, cudaFuncAttributeMaxDynamicSharedMemorySize,
                         (int)ATTN_SMEM);

    float* att;
    cudaGetSymbolAddress((void**)&att, g_att);

    qkv_kernel<<<dim3(3 * DM / 128, BB * TT / 128), 256>>>(x, w_qkv, b_qkv);
    attn_kernel<<<dim3(TT / 128, BH), 256, ATTN_SMEM>>>(mask, att);
    out_kernel<<<dim3(DM / 128, BB * TT / 128), 256>>>(att, w_out, b_out, out);
}

// round 4
// speedup vs baseline: 1.0942x; 1.0005x over previous
#include <cuda_runtime.h>

#define DM   768
#define NH   12
#define DH   64
#define BB   2
#define TT   4096
#define BH   (BB*NH)

// Scratch (no cudaMalloc allowed): Q/K/V in [B,H,T,Dh], att in [B,T,H,Dh]
__device__ float g_Q[(size_t)BH*TT*DH];
__device__ float g_K[(size_t)BH*TT*DH];
__device__ float g_V[(size_t)BH*TT*DH];
__device__ float g_att[(size_t)BB*TT*DM];

// ---------------------------------------------------------------------------
// GEMM1: qkv = x @ w_qkv^T + b_qkv, scattered into g_Q/g_K/g_V.
// 128x128 tile, K-tile 16, 256 threads, 8x8 per thread (1 B LDS per FMA).
// Q pre-scaled by 1/sqrt(64) = 0.125.
// ---------------------------------------------------------------------------
__global__ __launch_bounds__(256) void qkv_kernel(const float* __restrict__ x,
                                                  const float* __restrict__ w,
                                                  const float* __restrict__ bias) {
    __shared__ float As[16][128];
    __shared__ float Ws[16][128];
    const int tid = threadIdx.x;
    const int tx = tid & 15, ty = tid >> 4;
    const int n0 = blockIdx.x * 128, m0 = blockIdx.y * 128;
    const int lr = tid >> 2, lk = (tid & 3) * 4;

    const float* a0p = x + (size_t)(m0 + lr) * DM + lk;
    const float* a1p = a0p + (size_t)64 * DM;
    const float* w0p = w + (size_t)(n0 + lr) * DM + lk;
    const float* w1p = w0p + (size_t)64 * DM;

    float4 ra0 = *(const float4*)a0p;
    float4 ra1 = *(const float4*)a1p;
    float4 rw0 = *(const float4*)w0p;
    float4 rw1 = *(const float4*)w1p;

    float acc[8][8] = {};
    for (int k0 = 0; k0 < DM; k0 += 16) {
        As[lk + 0][lr] = ra0.x; As[lk + 1][lr] = ra0.y;
        As[lk + 2][lr] = ra0.z; As[lk + 3][lr] = ra0.w;
        As[lk + 0][lr + 64] = ra1.x; As[lk + 1][lr + 64] = ra1.y;
        As[lk + 2][lr + 64] = ra1.z; As[lk + 3][lr + 64] = ra1.w;
        Ws[lk + 0][lr] = rw0.x; Ws[lk + 1][lr] = rw0.y;
        Ws[lk + 2][lr] = rw0.z; Ws[lk + 3][lr] = rw0.w;
        Ws[lk + 0][lr + 64] = rw1.x; Ws[lk + 1][lr + 64] = rw1.y;
        Ws[lk + 2][lr + 64] = rw1.z; Ws[lk + 3][lr + 64] = rw1.w;
        __syncthreads();
        int knext = (k0 + 16 < DM) ? (k0 + 16) : 0;   // last prefetch harmless
        ra0 = *(const float4*)(a0p + knext);
        ra1 = *(const float4*)(a1p + knext);
        rw0 = *(const float4*)(w0p + knext);
        rw1 = *(const float4*)(w1p + knext);
#pragma unroll
        for (int k = 0; k < 16; k++) {
            float a[8], b[8];
            *(float4*)&a[0] = *(const float4*)&As[k][8 * ty];
            *(float4*)&a[4] = *(const float4*)&As[k][8 * ty + 4];
            *(float4*)&b[0] = *(const float4*)&Ws[k][8 * tx];
            *(float4*)&b[4] = *(const float4*)&Ws[k][8 * tx + 4];
#pragma unroll
            for (int i = 0; i < 8; i++)
#pragma unroll
                for (int j = 0; j < 8; j++)
                    acc[i][j] += a[i] * b[j];
        }
        __syncthreads();
    }

    const int g = n0 + 8 * tx;
    const int which = n0 / DM;              // 0=Q 1=K 2=V (tiles never straddle)
    const int head  = (g % DM) >> 6;
    const int d0    = g & 63;
    float* dst = (which == 0) ? g_Q : ((which == 1) ? g_K : g_V);
    const float scale = (which == 0) ? 0.125f : 1.0f;

    float bia[8];
    *(float4*)&bia[0] = *(const float4*)&bias[g];
    *(float4*)&bia[4] = *(const float4*)&bias[g + 4];

#pragma unroll
    for (int i = 0; i < 8; i++) {
        int m = m0 + 8 * ty + i;
        int bb = m >> 12, t = m & 4095;
        float* o = &dst[(((size_t)(bb * NH + head)) * TT + t) * DH + d0];
        float4 v0, v1;
        v0.x = (acc[i][0] + bia[0]) * scale; v0.y = (acc[i][1] + bia[1]) * scale;
        v0.z = (acc[i][2] + bia[2]) * scale; v0.w = (acc[i][3] + bia[3]) * scale;
        v1.x = (acc[i][4] + bia[4]) * scale; v1.y = (acc[i][5] + bia[5]) * scale;
        v1.z = (acc[i][6] + bia[6]) * scale; v1.w = (acc[i][7] + bia[7]) * scale;
        *(float4*)o = v0;
        *(float4*)(o + 4) = v1;
    }
}

// ---------------------------------------------------------------------------
// Flash attention: 128 q-rows x 128 k-cols per iteration, 256 threads.
// S phase: 8x8 fragments (rows 8ty+i, cols 8tx+j); softmax reduced over tx
//          lanes (in-warp shfl). P stored row-major, stride 132.
// PV phase: remapped 4x8 fragments (rows ro+32i, d-cols 8dx) -> conflict-free
//          float4 P reads and single-wavefront V reads. alpha/l cross the
//          mapping via smem.
// ---------------------------------------------------------------------------
__global__ __launch_bounds__(256) void attn_kernel(const int* __restrict__ mask,
                                                   float* __restrict__ att) {
    extern __shared__ float sm[];
    float* Qt = sm;                    // [64][128]  d-major
    float* Kt = Qt + 64 * 128;         // [64][128]  d-major
    float* Vs = Kt + 64 * 128;         // [128][64]  k-major
    float* Pt = Vs + 128 * 64;         // [128][132] q-major, padded
    float* alpha_s = Pt + 128 * 132;   // [128]

    const int tid = threadIdx.x;
    const int tx = tid & 15, ty = tid >> 4;   // S mapping
    const int dx = tid & 7,  ro = tid >> 3;   // PV mapping
    const int bh = blockIdx.y;
    const int b = bh / NH, head = bh % NH;
    const int q0 = blockIdx.x * 128;

    const float* Qp = g_Q + (size_t)bh * TT * DH;
    const float* Kp = g_K + (size_t)bh * TT * DH;
    const float* Vp = g_V + (size_t)bh * TT * DH;
    const int* mrow_g = mask + (size_t)b * TT;

    // load Q tile transposed (rows r, r+64)
    {
        int r = tid >> 2, d0 = (tid & 3) * 16;
#pragma unroll
        for (int h = 0; h < 2; h++) {
            int rr = r + 64 * h;
            const float* src = Qp + (size_t)(q0 + rr) * DH + d0;
#pragma unroll
            for (int u = 0; u < 4; u++) {
                float4 v = *(const float4*)(src + 4 * u);
                Qt[(d0 + 4 * u + 0) * 128 + rr] = v.x;
                Qt[(d0 + 4 * u + 1) * 128 + rr] = v.y;
                Qt[(d0 + 4 * u + 2) * 128 + rr] = v.z;
                Qt[(d0 + 4 * u + 3) * 128 + rr] = v.w;
            }
        }
    }

    float O[4][8] = {};
    float mr[8], lw[8];
#pragma unroll
    for (int i = 0; i < 8; i++) { mr[i] = -1e30f; lw[i] = 0.f; }

    for (int jt = 0; jt < TT / 128; jt++) {
        __syncthreads();   // prev PV done; (iter 0: Qt load visible after next)
        {
            int r = tid >> 2, d0 = (tid & 3) * 16;
#pragma unroll
            for (int h = 0; h < 2; h++) {
                int rr = r + 64 * h;
                const float* ks = Kp + (size_t)(jt * 128 + rr) * DH + d0;
                const float* vs = Vp + (size_t)(jt * 128 + rr) * DH + d0;
#pragma unroll
                for (int u = 0; u < 4; u++) {
                    float4 kv = *(const float4*)(ks + 4 * u);
                    Kt[(d0 + 4 * u + 0) * 128 + rr] = kv.x;
                    Kt[(d0 + 4 * u + 1) * 128 + rr] = kv.y;
                    Kt[(d0 + 4 * u + 2) * 128 + rr] = kv.z;
                    Kt[(d0 + 4 * u + 3) * 128 + rr] = kv.w;
                    *(float4*)&Vs[rr * 64 + d0 + 4 * u] = *(const float4*)(vs + 4 * u);
                }
            }
        }
        int msk[8];
        {
            const int* mp = mrow_g + jt * 128 + 8 * tx;
            *(int4*)&msk[0] = *(const int4*)mp;
            *(int4*)&msk[4] = *(const int4*)(mp + 4);
        }
        __syncthreads();

        // S = Q @ K^T  (Q pre-scaled)
        float s[8][8] = {};
#pragma unroll 8
        for (int d = 0; d < 64; d++) {
            float q[8], k[8];
            *(float4*)&q[0] = *(const float4*)&Qt[d * 128 + 8 * ty];
            *(float4*)&q[4] = *(const float4*)&Qt[d * 128 + 8 * ty + 4];
            *(float4*)&k[0] = *(const float4*)&Kt[d * 128 + 8 * tx];
            *(float4*)&k[4] = *(const float4*)&Kt[d * 128 + 8 * tx + 4];
#pragma unroll
            for (int i = 0; i < 8; i++)
#pragma unroll
                for (int j = 0; j < 8; j++)
                    s[i][j] += q[i] * k[j];
        }
#pragma unroll
        for (int j = 0; j < 8; j++) {
            if (msk[j] == 0) {
#pragma unroll
                for (int i = 0; i < 8; i++) s[i][j] = -1e9f;
            }
        }

        // online softmax (rows 8ty+i), reduce over tx lanes
#pragma unroll
        for (int i = 0; i < 8; i++) {
            float mx = s[i][0];
#pragma unroll
            for (int j = 1; j < 8; j++) mx = fmaxf(mx, s[i][j]);
            mx = fmaxf(mx, __shfl_xor_sync(0xffffffffu, mx, 1));
            mx = fmaxf(mx, __shfl_xor_sync(0xffffffffu, mx, 2));
            mx = fmaxf(mx, __shfl_xor_sync(0xffffffffu, mx, 4));
            mx = fmaxf(mx, __shfl_xor_sync(0xffffffffu, mx, 8));
            float mnew = fmaxf(mr[i], mx);
            float al = __expf(mr[i] - mnew);
            float sum = 0.f;
#pragma unroll
            for (int j = 0; j < 8; j++) {
                s[i][j] = __expf(s[i][j] - mnew);
                sum += s[i][j];
            }
            sum += __shfl_xor_sync(0xffffffffu, sum, 1);
            sum += __shfl_xor_sync(0xffffffffu, sum, 2);
            sum += __shfl_xor_sync(0xffffffffu, sum, 4);
            sum += __shfl_xor_sync(0xffffffffu, sum, 8);
            lw[i] = lw[i] * al + sum;
            mr[i] = mnew;
            if (tx == 0) alpha_s[8 * ty + i] = al;
            float* prow = &Pt[(8 * ty + i) * 132 + 8 * tx];
            *(float4*)prow       = make_float4(s[i][0], s[i][1], s[i][2], s[i][3]);
            *(float4*)(prow + 4) = make_float4(s[i][4], s[i][5], s[i][6], s[i][7]);
        }
        __syncthreads();

        // O = O*alpha + P @ V   (rows ro+32i, cols 8dx..8dx+7)
        float al4[4];
#pragma unroll
        for (int i = 0; i < 4; i++) al4[i] = alpha_s[ro + 32 * i];
#pragma unroll
        for (int i = 0; i < 4; i++)
#pragma unroll
            for (int j = 0; j < 8; j++) O[i][j] *= al4[i];

#pragma unroll 2
        for (int k4 = 0; k4 < 128; k4 += 4) {
            float p[4][4];
#pragma unroll
            for (int i = 0; i < 4; i++)
                *(float4*)p[i] = *(const float4*)&Pt[(ro + 32 * i) * 132 + k4];
#pragma unroll
            for (int u = 0; u < 4; u++) {
                float v[8];
                *(float4*)&v[0] = *(const float4*)&Vs[(k4 + u) * 64 + 8 * dx];
                *(float4*)&v[4] = *(const float4*)&Vs[(k4 + u) * 64 + 8 * dx + 4];
#pragma unroll
                for (int i = 0; i < 4; i++)
#pragma unroll
                    for (int j = 0; j < 8; j++)
                        O[i][j] += p[i][u] * v[j];
            }
        }
    }

    // epilogue: 1/l across the mapping, then store [B,T,H,Dh]
    __syncthreads();
    if (tx == 0) {
#pragma unroll
        for (int i = 0; i < 8; i++) alpha_s[8 * ty + i] = 1.0f / lw[i];
    }
    __syncthreads();
#pragma unroll
    for (int i = 0; i < 4; i++) {
        float inv = alpha_s[ro + 32 * i];
        int t = q0 + ro + 32 * i;
        float* o = att + (((size_t)b * TT + t) * NH + head) * DH + 8 * dx;
        float4 v0, v1;
        v0.x = O[i][0] * inv; v0.y = O[i][1] * inv;
        v0.z = O[i][2] * inv; v0.w = O[i][3] * inv;
        v1.x = O[i][4] * inv; v1.y = O[i][5] * inv;
        v1.z = O[i][6] * inv; v1.w = O[i][7] * inv;
        *(float4*)o = v0;
        *(float4*)(o + 4) = v1;
    }
}

// ---------------------------------------------------------------------------
// GEMM2: out = att @ w_out^T + b_out. Same 128x128x16 microkernel.
// ---------------------------------------------------------------------------
__global__ __launch_bounds__(256) void out_kernel(const float* __restrict__ a_in,
                                                  const float* __restrict__ w,
                                                  const float* __restrict__ bias,
                                                  float* __restrict__ out) {
    __shared__ float As[16][128];
    __shared__ float Ws[16][128];
    const int tid = threadIdx.x;
    const int tx = tid & 15, ty = tid >> 4;
    const int n0 = blockIdx.x * 128, m0 = blockIdx.y * 128;
    const int lr = tid >> 2, lk = (tid & 3) * 4;

    const float* a0p = a_in + (size_t)(m0 + lr) * DM + lk;
    const float* a1p = a0p + (size_t)64 * DM;
    const float* w0p = w + (size_t)(n0 + lr) * DM + lk;
    const float* w1p = w0p + (size_t)64 * DM;

    float4 ra0 = *(const float4*)a0p;
    float4 ra1 = *(const float4*)a1p;
    float4 rw0 = *(const float4*)w0p;
    float4 rw1 = *(const float4*)w1p;

    float acc[8][8] = {};
    for (int k0 = 0; k0 < DM; k0 += 16) {
        As[lk + 0][lr] = ra0.x; As[lk + 1][lr] = ra0.y;
        As[lk + 2][lr] = ra0.z; As[lk + 3][lr] = ra0.w;
        As[lk + 0][lr + 64] = ra1.x; As[lk + 1][lr + 64] = ra1.y;
        As[lk + 2][lr + 64] = ra1.z; As[lk + 3][lr + 64] = ra1.w;
        Ws[lk + 0][lr] = rw0.x; Ws[lk + 1][lr] = rw0.y;
        Ws[lk + 2][lr] = rw0.z; Ws[lk + 3][lr] = rw0.w;
        Ws[lk + 0][lr + 64] = rw1.x; Ws[lk + 1][lr + 64] = rw1.y;
        Ws[lk + 2][lr + 64] = rw1.z; Ws[lk + 3][lr + 64] = rw1.w;
        __syncthreads();
        int knext = (k0 + 16 < DM) ? (k0 + 16) : 0;
        ra0 = *(const float4*)(a0p + knext);
        ra1 = *(const float4*)(a1p + knext);
        rw0 = *(const float4*)(w0p + knext);
        rw1 = *(const float4*)(w1p + knext);
#pragma unroll
        for (int k = 0; k < 16; k++) {
            float a[8], b[8];
            *(float4*)&a[0] = *(const float4*)&As[k][8 * ty];
            *(float4*)&a[4] = *(const float4*)&As[k][8 * ty + 4];
            *(float4*)&b[0] = *(const float4*)&Ws[k][8 * tx];
            *(float4*)&b[4] = *(const float4*)&Ws[k][8 * tx + 4];
#pragma unroll
            for (int i = 0; i < 8; i++)
#pragma unroll
                for (int j = 0; j < 8; j++)
                    acc[i][j] += a[i] * b[j];
        }
        __syncthreads();
    }

    float bia[8];
    *(float4*)&bia[0] = *(const float4*)&bias[n0 + 8 * tx];
    *(float4*)&bia[4] = *(const float4*)&bias[n0 + 8 * tx + 4];

#pragma unroll
    for (int i = 0; i < 8; i++) {
        int m = m0 + 8 * ty + i;
        float* o = &out[(size_t)m * DM + n0 + 8 * tx];
        float4 v0, v1;
        v0.x = acc[i][0] + bia[0]; v0.y = acc[i][1] + bia[1];
        v0.z = acc[i][2] + bia[2]; v0.w = acc[i][3] + bia[3];
        v1.x = acc[i][4] + bia[4]; v1.y = acc[i][5] + bia[5];
        v1.z = acc[i][6] + bia[6]; v1.w = acc[i][7] + bia[7];
        *(float4*)o = v0;
        *(float4*)(o + 4) = v1;
    }
}

// ---------------------------------------------------------------------------
// Inputs (metadata order): x, w_qkv, b_qkv, w_out, b_out, mask. Output: float32.
// ---------------------------------------------------------------------------
extern "C" void kernel_launch(void* const* d_in, const int* in_sizes, int n_in,
                              void* d_out, int out_size) {
    const float* x     = (const float*)d_in[0];
    const float* w_qkv = (const float*)d_in[1];
    const float* b_qkv = (const float*)d_in[2];
    const float* w_out = (const float*)d_in[3];
    const float* b_out = (const float*)d_in[4];
    const int*   mask  = (const int*)d_in[5];
    float* out = (float*)d_out;

    static const size_t ATTN_SMEM =
        (2 * 64 * 128 + 128 * 64 + 128 * 132 + 128) * sizeof(float); // 166912 B
    cudaFuncSetAttribute(attn_kernel, cudaFuncAttributeMaxDynamicSharedMemorySize,
                         (int)ATTN_SMEM);

    float* att;
    cudaGetSymbolAddress((void**)&att, g_att);

    qkv_kernel<<<dim3(3 * DM / 128, BB * TT / 128), 256>>>(x, w_qkv, b_qkv);
    attn_kernel<<<dim3(TT / 128, BH), 256, ATTN_SMEM>>>(mask, att);
    out_kernel<<<dim3(DM / 128, BB * TT / 128), 256>>>(att, w_out, b_out, out);
}